// round 1
// baseline (speedup 1.0000x reference)
#include <cuda_runtime.h>
#include <stdint.h>

// Problem constants (fixed by the dataset).
#define BATCH 4
#define HEADS 32
#define SEQ   4096
#define DK    128
#define HALF  (DK / 2)          // 64 rotation pairs
#define VEC_PER_ROW (DK / 4)    // 32 float4 per d_k row

// 2 MB scratch: per (seq position, pair-group of 2) -> (c0, s0, c1, s1)
__device__ float4 g_cs[SEQ * VEC_PER_ROW];

// Kernel A: gather cos/sin from the block-diagonal R using token_positions.
// R layout: [MAX_SEQ_LEN, 128, 128] row-major.
//   c = R[pos, 2p,   2p]
//   s = R[pos, 2p+1, 2p]
__global__ void build_cs_table(const float* __restrict__ R,
                               const int* __restrict__ token_positions) {
    int tid = blockIdx.x * blockDim.x + threadIdx.x;   // over SEQ * HALF
    if (tid >= SEQ * HALF) return;
    int p = tid & (HALF - 1);
    int s = tid >> 6;                                   // tid / HALF
    long long pos = token_positions[s];
    const float* Rp = R + pos * (long long)(DK * DK);
    float c  = Rp[(2 * p) * DK + 2 * p];
    float sv = Rp[(2 * p + 1) * DK + 2 * p];
    // store as float2 into the float4 table (pair p -> half of group p/2)
    float2* cs2 = reinterpret_cast<float2*>(g_cs);
    cs2[s * HALF + p] = make_float2(c, sv);
}

// Kernel B: vectorized RoPE.
// out[2p]   = c*x[2p] - s*x[2p+1]
// out[2p+1] = s*x[2p] + c*x[2p+1]
__global__ void __launch_bounds__(256)
rope_kernel(const float4* __restrict__ x, float4* __restrict__ out) {
    long long v = (long long)blockIdx.x * blockDim.x + threadIdx.x;
    // total float4 elements = BATCH*HEADS*SEQ*VEC_PER_ROW = 16,777,216 (exact grid)
    int d4 = (int)(v & (VEC_PER_ROW - 1));              // which float4 in the row
    int s  = (int)((v >> 5) & (SEQ - 1));               // sequence position

    float4 cs = g_cs[s * VEC_PER_ROW + d4];             // (c0, s0, c1, s1) — L2 hit
    float4 xi = x[v];

    float4 o;
    o.x = fmaf(cs.x, xi.x, -cs.y * xi.y);
    o.y = fmaf(cs.y, xi.x,  cs.x * xi.y);
    o.z = fmaf(cs.z, xi.z, -cs.w * xi.w);
    o.w = fmaf(cs.w, xi.z,  cs.z * xi.w);
    out[v] = o;
}

extern "C" void kernel_launch(void* const* d_in, const int* in_sizes, int n_in,
                              void* d_out, int out_size) {
    const float* x   = (const float*)d_in[0];
    const int*   tp  = (const int*)d_in[1];
    const float* R   = (const float*)d_in[2];
    float* out = (float*)d_out;

    // Kernel A: 4096*64 = 262144 threads
    build_cs_table<<<(SEQ * HALF + 255) / 256, 256>>>(R, tp);

    // Kernel B: 16,777,216 float4 -> 65536 blocks of 256
    long long total_vec = (long long)BATCH * HEADS * SEQ * VEC_PER_ROW;
    int blocks = (int)(total_vec / 256);
    rope_kernel<<<blocks, 256>>>((const float4*)x, (float4*)out);
}

// round 2
// speedup vs baseline: 1.0269x; 1.0269x over previous
#include <cuda_runtime.h>
#include <stdint.h>

#define BATCH 4
#define HEADS 32
#define SEQ   4096
#define DK    128
#define HALF  (DK / 2)          // 64 rotation pairs
#define VEC_PER_ROW (DK / 4)    // 32 float4 per d_k row
#define BH (BATCH * HEADS)      // 128 batch-head slices
#define BH_PER_THREAD 4
#define PLANE (SEQ * VEC_PER_ROW)   // 131072 float4 per bh slice

// 2 MB scratch: per (seq position, float4-group) -> (c0, s0, c1, s1)
__device__ float4 g_cs[SEQ * VEC_PER_ROW];

// Kernel A: gather cos/sin from block-diagonal R via token_positions.
//   c = R[pos, 2p,   2p], s = R[pos, 2p+1, 2p]
__global__ void build_cs_table(const float* __restrict__ R,
                               const int* __restrict__ token_positions) {
    int tid = blockIdx.x * blockDim.x + threadIdx.x;   // over SEQ * HALF
    if (tid >= SEQ * HALF) return;
    int p = tid & (HALF - 1);
    int s = tid >> 6;
    long long pos = token_positions[s];
    const float* Rp = R + pos * (long long)(DK * DK);
    float c  = __ldg(&Rp[(2 * p) * DK + 2 * p]);
    float sv = __ldg(&Rp[(2 * p + 1) * DK + 2 * p]);
    float2* cs2 = reinterpret_cast<float2*>(g_cs);
    cs2[s * HALF + p] = make_float2(c, sv);
}

// Kernel B: each thread handles one (s, d4) slot across 4 batch-head slices.
// 1 table load (L2-resident), 4 streamed x loads, 4 streamed stores.
__global__ void __launch_bounds__(256)
rope_kernel(const float4* __restrict__ x, float4* __restrict__ out) {
    unsigned t = blockIdx.x * blockDim.x + threadIdx.x;  // 0 .. 4,194,303
    unsigned r   = t & (PLANE - 1);                      // (s, d4) within a slice
    unsigned bh4 = t >> 17;                              // which group of 4 slices

    float4 cs = g_cs[r];                                 // L2 hit (2 MB table)

    unsigned base = bh4 * (4u * PLANE) + r;

    // Front-batch the 4 independent loads for MLP.
    float4 x0 = __ldcs(&x[base + 0u * PLANE]);
    float4 x1 = __ldcs(&x[base + 1u * PLANE]);
    float4 x2 = __ldcs(&x[base + 2u * PLANE]);
    float4 x3 = __ldcs(&x[base + 3u * PLANE]);

    float4 o0, o1, o2, o3;
    #define ROT(o, xi)                                  \
        o.x = fmaf(cs.x, xi.x, -cs.y * xi.y);           \
        o.y = fmaf(cs.y, xi.x,  cs.x * xi.y);           \
        o.z = fmaf(cs.z, xi.z, -cs.w * xi.w);           \
        o.w = fmaf(cs.w, xi.z,  cs.z * xi.w);
    ROT(o0, x0) ROT(o1, x1) ROT(o2, x2) ROT(o3, x3)
    #undef ROT

    __stcs(&out[base + 0u * PLANE], o0);
    __stcs(&out[base + 1u * PLANE], o1);
    __stcs(&out[base + 2u * PLANE], o2);
    __stcs(&out[base + 3u * PLANE], o3);
}

extern "C" void kernel_launch(void* const* d_in, const int* in_sizes, int n_in,
                              void* d_out, int out_size) {
    const float* x  = (const float*)d_in[0];
    const int*   tp = (const int*)d_in[1];
    const float* R  = (const float*)d_in[2];
    float* out = (float*)d_out;

    build_cs_table<<<(SEQ * HALF + 255) / 256, 256>>>(R, tp);

    // threads = BH/4 * PLANE = 32 * 131072 = 4,194,304 -> 16384 blocks
    unsigned total_threads = (BH / BH_PER_THREAD) * PLANE;
    rope_kernel<<<total_threads / 256, 256>>>((const float4*)x, (float4*)out);
}